// round 4
// baseline (speedup 1.0000x reference)
#include <cuda_runtime.h>
#include <cuda_bf16.h>

#define LN_EPS 1e-5f
#define ROWS_PER_BLOCK 4
#define WARPS_PER_ROW 3
#define THREADS_PER_ROW (WARPS_PER_ROW * 32)          // 96
#define BLOCK_THREADS (ROWS_PER_BLOCK * THREADS_PER_ROW)  // 384

static __device__ __forceinline__ float warp_sum(float v) {
#pragma unroll
    for (int o = 16; o; o >>= 1) v += __shfl_xor_sync(0xffffffffu, v, o);
    return v;
}

// 3 warps per output row (b, t): 96 lanes x 2 float4 = 192 float4 = H=768.
// Register-cached row + pos/type; shuffle reduce within warp, one smem
// exchange + one __syncthreads across the 3 warps of a row.
__global__ void __launch_bounds__(BLOCK_THREADS)
prev_embedding_kernel(
    const float* __restrict__ cv,    // [V, H]
    const float* __restrict__ ocr,   // [B, N, H]
    const int*   __restrict__ ids,   // [B, T]
    const float* __restrict__ cvg, const float* __restrict__ cvb,
    const float* __restrict__ og,  const float* __restrict__ ob,
    const float* __restrict__ pos,   // [T, H]
    const float* __restrict__ typ,   // [2, H]
    const float* __restrict__ eg,  const float* __restrict__ eb,
    float* __restrict__ out,         // [B, T, H]
    int V, int N, int T, int H, int BT)
{
    const int tid   = threadIdx.x;
    const int wid   = tid >> 5;                  // 0..11
    const int row_l = tid / THREADS_PER_ROW;     // 0..3 row within block
    const int l96   = tid - row_l * THREADS_PER_ROW;  // 0..95 lane within row

    int wrow = blockIdx.x * ROWS_PER_BLOCK + row_l;
    const bool valid = (wrow < BT);
    if (wrow >= BT) wrow = BT - 1;               // clamp; all threads reach barrier

    const int b = wrow / T;
    const int t = wrow - b * T;

    const int id = __ldg(ids + wrow);
    const float* src;
    const float* gam;
    const float* bet;
    if (id >= V) {
        int oi = id - V;
        oi = max(0, min(oi, N - 1));
        src = ocr + ((size_t)b * (size_t)N + (size_t)oi) * (size_t)H;
        gam = og; bet = ob;
    } else {
        int ci = max(0, min(id, V - 1));
        src = cv + (size_t)ci * (size_t)H;
        gam = cvg; bet = cvb;
    }

    const float4* s4 = (const float4*)src;
    const float4* p4 = (const float4*)(pos + (size_t)t * (size_t)H);
    const float4* t4 = (const float4*)(typ + ((t >= V) ? (size_t)H : (size_t)0));

    // H=768 -> 192 float4; 96 lanes/row -> 2 per lane (front-batched LDG.128).
    float4 a[2], p[2];
#pragma unroll
    for (int i = 0; i < 2; i++) {
        const int idx = l96 + THREADS_PER_ROW * i;
        a[i] = s4[idx];
        float4 pp = p4[idx];
        float4 tt = t4[idx];
        p[i] = make_float4(pp.x + tt.x, pp.y + tt.y, pp.z + tt.z, pp.w + tt.w);
    }

    float sa = 0.f, ssa = 0.f, sp = 0.f, ssp = 0.f;
#pragma unroll
    for (int i = 0; i < 2; i++) {
        sa  += a[i].x + a[i].y + a[i].z + a[i].w;
        ssa += a[i].x * a[i].x + a[i].y * a[i].y + a[i].z * a[i].z + a[i].w * a[i].w;
        sp  += p[i].x + p[i].y + p[i].z + p[i].w;
        ssp += p[i].x * p[i].x + p[i].y * p[i].y + p[i].z * p[i].z + p[i].w * p[i].w;
    }
    sa = warp_sum(sa); ssa = warp_sum(ssa); sp = warp_sum(sp); ssp = warp_sum(ssp);

    __shared__ float4 red[ROWS_PER_BLOCK * WARPS_PER_ROW];
    if ((tid & 31) == 0) red[wid] = make_float4(sa, ssa, sp, ssp);
    __syncthreads();

    // Sum the 3 warp-partials of this row (broadcast smem reads, conflict-free).
    const int base = row_l * WARPS_PER_ROW;
    float4 r0 = red[base], r1 = red[base + 1], r2 = red[base + 2];
    sa  = r0.x + r1.x + r2.x;
    ssa = r0.y + r1.y + r2.y;
    sp  = r0.z + r1.z + r2.z;
    ssp = r0.w + r1.w + r2.w;

    const float invH = 1.0f / (float)H;
    const float mua = sa * invH;
    const float va  = fmaf(-mua, mua, ssa * invH);
    const float mup = sp * invH;
    const float vp  = fmaf(-mup, mup, ssp * invH);
    const float ra  = rsqrtf(va + LN_EPS);
    const float rp  = rsqrtf(vp + LN_EPS);

    if (!valid) return;

    float4* o4 = (float4*)(out + (size_t)wrow * (size_t)H);
#pragma unroll
    for (int i = 0; i < 2; i++) {
        const int idx = l96 + THREADS_PER_ROW * i;
        const float4 g4  = ((const float4*)gam)[idx];
        const float4 b4  = ((const float4*)bet)[idx];
        const float4 eg4 = ((const float4*)eg)[idx];
        const float4 eb4 = ((const float4*)eb)[idx];
        float4 r;
        r.x = (a[i].x - mua) * ra * g4.x + b4.x + (p[i].x - mup) * rp * eg4.x + eb4.x;
        r.y = (a[i].y - mua) * ra * g4.y + b4.y + (p[i].y - mup) * rp * eg4.y + eb4.y;
        r.z = (a[i].z - mua) * ra * g4.z + b4.z + (p[i].z - mup) * rp * eg4.z + eb4.z;
        r.w = (a[i].w - mua) * ra * g4.w + b4.w + (p[i].w - mup) * rp * eg4.w + eb4.w;
        o4[idx] = r;
    }
}

extern "C" void kernel_launch(void* const* d_in, const int* in_sizes, int n_in,
                              void* d_out, int out_size) {
    const float* cv  = (const float*)d_in[0];
    const float* ocr = (const float*)d_in[1];
    const int*   ids = (const int*)d_in[2];
    const float* cvg = (const float*)d_in[3];
    const float* cvb = (const float*)d_in[4];
    const float* og  = (const float*)d_in[5];
    const float* ob  = (const float*)d_in[6];
    const float* pos = (const float*)d_in[7];
    const float* typ = (const float*)d_in[8];
    const float* eg  = (const float*)d_in[9];
    const float* eb  = (const float*)d_in[10];
    float* out = (float*)d_out;

    const int H  = in_sizes[3];
    const int V  = in_sizes[0] / H;
    const int T  = in_sizes[7] / H;
    const int BT = in_sizes[2];       // B * T
    const int B  = BT / T;
    const int N  = in_sizes[1] / (B * H);

    const int blocks = (BT + ROWS_PER_BLOCK - 1) / ROWS_PER_BLOCK;
    prev_embedding_kernel<<<blocks, BLOCK_THREADS>>>(
        cv, ocr, ids, cvg, cvb, og, ob, pos, typ, eg, eb, out, V, N, T, H, BT);
}

// round 6
// speedup vs baseline: 1.1333x; 1.1333x over previous
#include <cuda_runtime.h>
#include <cuda_bf16.h>

#define LN_EPS 1e-5f

static __device__ __forceinline__ float warp_sum(float v) {
#pragma unroll
    for (int o = 16; o; o >>= 1) v += __shfl_xor_sync(0xffffffffu, v, o);
    return v;
}

// One BLOCK (192 threads = 6 warps) per output row (b, t).
// H=768 -> 192 float4 -> exactly ONE float4 per lane per stream.
// Single global read pass (row register-cached), warp-shuffle partials,
// one __syncthreads, broadcast smem combine. Row-scoped sync: rows decoupled.
__global__ void __launch_bounds__(192, 10)
prev_embedding_kernel(
    const float* __restrict__ cv,    // [V, H]
    const float* __restrict__ ocr,   // [B, N, H]
    const int*   __restrict__ ids,   // [B, T]
    const float* __restrict__ cvg, const float* __restrict__ cvb,
    const float* __restrict__ og,  const float* __restrict__ ob,
    const float* __restrict__ pos,   // [T, H]
    const float* __restrict__ typ,   // [2, H]
    const float* __restrict__ eg,  const float* __restrict__ eb,
    float* __restrict__ out,         // [B, T, H]
    int V, int N, int T, int H)
{
    const int bt = blockIdx.x;
    const int l  = threadIdx.x;          // 0..191
    const int b  = bt / T;
    const int t  = bt - b * T;

    const int id = __ldg(ids + bt);
    const float* src;
    const float* gam;
    const float* bet;
    if (id >= V) {
        int oi = id - V;
        oi = max(0, min(oi, N - 1));
        src = ocr + ((size_t)b * (size_t)N + (size_t)oi) * (size_t)H;
        gam = og; bet = ob;
    } else {
        int ci = max(0, min(id, V - 1));
        src = cv + (size_t)ci * (size_t)H;
        gam = cvg; bet = cvb;
    }

    // One float4 per lane per stream (fully coalesced, front-batched).
    const float4 a = ((const float4*)src)[l];
    const float4 pp = ((const float4*)(pos + (size_t)t * (size_t)H))[l];
    const float4 tt = ((const float4*)(typ + ((t >= V) ? (size_t)H : (size_t)0)))[l];
    const float4 p = make_float4(pp.x + tt.x, pp.y + tt.y, pp.z + tt.z, pp.w + tt.w);

    float sa  = a.x + a.y + a.z + a.w;
    float ssa = a.x * a.x + a.y * a.y + a.z * a.z + a.w * a.w;
    float sp  = p.x + p.y + p.z + p.w;
    float ssp = p.x * p.x + p.y * p.y + p.z * p.z + p.w * p.w;

    sa = warp_sum(sa); ssa = warp_sum(ssa); sp = warp_sum(sp); ssp = warp_sum(ssp);

    __shared__ float4 red[6];
    const int w = l >> 5;
    if ((l & 31) == 0) red[w] = make_float4(sa, ssa, sp, ssp);
    __syncthreads();

    // All threads sum the 6 warp partials (broadcast smem reads).
    float4 r0 = red[0], r1 = red[1], r2 = red[2];
    float4 r3 = red[3], r4 = red[4], r5 = red[5];
    sa  = ((r0.x + r1.x) + (r2.x + r3.x)) + (r4.x + r5.x);
    ssa = ((r0.y + r1.y) + (r2.y + r3.y)) + (r4.y + r5.y);
    sp  = ((r0.z + r1.z) + (r2.z + r3.z)) + (r4.z + r5.z);
    ssp = ((r0.w + r1.w) + (r2.w + r3.w)) + (r4.w + r5.w);

    const float invH = 1.0f / (float)H;
    const float mua = sa * invH;
    const float va  = fmaf(-mua, mua, ssa * invH);
    const float mup = sp * invH;
    const float vp  = fmaf(-mup, mup, ssp * invH);
    const float ra  = rsqrtf(va + LN_EPS);
    const float rp  = rsqrtf(vp + LN_EPS);

    // Epilogue: row data from registers; gamma/beta streams are L1/L2-hot.
    const float4 g4  = ((const float4*)gam)[l];
    const float4 b4  = ((const float4*)bet)[l];
    const float4 eg4 = ((const float4*)eg)[l];
    const float4 eb4 = ((const float4*)eb)[l];
    float4 r;
    r.x = (a.x - mua) * ra * g4.x + b4.x + (p.x - mup) * rp * eg4.x + eb4.x;
    r.y = (a.y - mua) * ra * g4.y + b4.y + (p.y - mup) * rp * eg4.y + eb4.y;
    r.z = (a.z - mua) * ra * g4.z + b4.z + (p.z - mup) * rp * eg4.z + eb4.z;
    r.w = (a.w - mua) * ra * g4.w + b4.w + (p.w - mup) * rp * eg4.w + eb4.w;
    ((float4*)(out + (size_t)bt * (size_t)H))[l] = r;
}

extern "C" void kernel_launch(void* const* d_in, const int* in_sizes, int n_in,
                              void* d_out, int out_size) {
    const float* cv  = (const float*)d_in[0];
    const float* ocr = (const float*)d_in[1];
    const int*   ids = (const int*)d_in[2];
    const float* cvg = (const float*)d_in[3];
    const float* cvb = (const float*)d_in[4];
    const float* og  = (const float*)d_in[5];
    const float* ob  = (const float*)d_in[6];
    const float* pos = (const float*)d_in[7];
    const float* typ = (const float*)d_in[8];
    const float* eg  = (const float*)d_in[9];
    const float* eb  = (const float*)d_in[10];
    float* out = (float*)d_out;

    const int H  = in_sizes[3];
    const int V  = in_sizes[0] / H;
    const int T  = in_sizes[7] / H;
    const int BT = in_sizes[2];       // B * T
    const int B  = BT / T;
    const int N  = in_sizes[1] / (B * H);

    // H=768 exactly -> 192 threads, one float4 per lane.
    prev_embedding_kernel<<<BT, H / 4>>>(
        cv, ocr, ids, cvg, cvb, og, ob, pos, typ, eg, eb, out, V, N, T, H);
}